// round 1
// baseline (speedup 1.0000x reference)
#include <cuda_runtime.h>

#define CUTOFF_INV_PI (3.14159265358979323846f / 6.0f)

__device__ __forceinline__ float fc(float R) {
    return fmaf(0.5f, __cosf(CUTOFF_INV_PI * R), 0.5f);
}

__global__ void zero_kernel(float* __restrict__ out, int n) {
    int i = blockIdx.x * blockDim.x + threadIdx.x;
    if (i < n) out[i] = 0.0f;
}

// G2: one thread per edge, 8 atomic adds into out[tgt*70 + e*2 + an_src]
__global__ void g2_kernel(const int* __restrict__ an,
                          const int* __restrict__ ei,
                          const float* __restrict__ D,
                          const float* __restrict__ g2_etas,
                          float* __restrict__ out, int E) {
    int e = blockIdx.x * blockDim.x + threadIdx.x;
    if (e >= E) return;
    int src = ei[e];
    int tgt = ei[E + e];
    int s = an[src];
    int t = an[tgt];
    float d = D[e];
    float c = fc(d);
    float d2 = d * d;
    const float* eta = g2_etas + (s * 2 + t) * 8;
    float* o = out + tgt * 70 + s;
#pragma unroll
    for (int k = 0; k < 8; k++) {
        atomicAdd(o + 2 * k, c * __expf(-eta[k] * d2));
    }
}

// G4: one thread per triplet, 18 atomic adds into the central atom's row
__global__ void g4_kernel(const int* __restrict__ an,
                          const int* __restrict__ ei,
                          const float* __restrict__ D,
                          const int* __restrict__ id3_ba,
                          const int* __restrict__ id3_ca,
                          const float* __restrict__ cosphi,
                          const float* __restrict__ g4_etas,
                          const float* __restrict__ g4_zetas,
                          const float* __restrict__ g4_lmdas,
                          float* __restrict__ out, int T, int E) {
    int i = blockIdx.x * blockDim.x + threadIdx.x;
    if (i >= T) return;
    int ba = id3_ba[i];
    int ca = id3_ca[i];
    if (ba <= ca) return;  // m3 dedup mask

    float Rba = D[ba];
    float Rca = D[ca];
    float cph = cosphi[i];

    float Rbc2 = fmaf(Rba, Rba, fmaf(Rca, Rca, -2.0f * Rba * Rca * cph));
    float Rbc = sqrtf(fmaxf(Rbc2, 1e-12f));
    if (Rbc >= 6.0f || Rba >= 6.0f || Rca >= 6.0f) return;  // in_range

    float cut3 = fc(Rca) * fc(Rbc) * fc(Rba);
    float r2sum = Rbc * Rbc + Rba * Rba + Rca * Rca;

    int sb = an[ei[ba]];
    int aidx = ei[E + ba];       // central atom index
    int A = an[aidx];
    int sc = an[ei[ca]];
    int t = min(sb, sc) + max(sb, sc);  // trip index: (0,0)->0 (0,1)->1 (1,1)->2
    int k4 = A * 3 + t;

    const float* eta = g4_etas + k4 * 3;
    const float* zta = g4_zetas + k4 * 3;
    const float* lmd = g4_lmdas + k4 * 2;

    float rad[3];
#pragma unroll
    for (int ii = 0; ii < 3; ii++)
        rad[ii] = __expf(-eta[ii] * r2sum) * cut3;

    float cl[2][3];
#pragma unroll
    for (int j = 0; j < 2; j++) {
        float base = fmaxf(fabsf(fmaf(lmd[j], cph, 1.0f)), 1e-38f);
        float lb = __log2f(base);
#pragma unroll
        for (int kk = 0; kk < 3; kk++) {
            float z = zta[kk];
            // 2^(1-z) * base^z = exp2(z*lb + 1 - z)
            cl[j][kk] = exp2f(fmaf(z, lb, 1.0f - z));
        }
    }

    float* o = out + aidx * 70 + 16 + t;
#pragma unroll
    for (int ii = 0; ii < 3; ii++)
#pragma unroll
        for (int j = 0; j < 2; j++)
#pragma unroll
            for (int kk = 0; kk < 3; kk++)
                atomicAdd(o + ((ii * 2 + j) * 3 + kk) * 3, rad[ii] * cl[j][kk]);
}

extern "C" void kernel_launch(void* const* d_in, const int* in_sizes, int n_in,
                              void* d_out, int out_size) {
    const int*   an      = (const int*)  d_in[0];
    const int*   ei      = (const int*)  d_in[1];
    const float* D       = (const float*)d_in[2];
    const int*   id3_ba  = (const int*)  d_in[3];
    const int*   id3_ca  = (const int*)  d_in[4];
    const float* cosphi  = (const float*)d_in[5];
    const float* g2_etas = (const float*)d_in[6];
    const float* g4_etas = (const float*)d_in[7];
    const float* g4_zetas= (const float*)d_in[8];
    const float* g4_lmdas= (const float*)d_in[9];

    int E = in_sizes[2];
    int T = in_sizes[3];
    float* out = (float*)d_out;

    zero_kernel<<<(out_size + 255) / 256, 256>>>(out, out_size);
    g2_kernel<<<(E + 255) / 256, 256>>>(an, ei, D, g2_etas, out, E);
    g4_kernel<<<(T + 255) / 256, 256>>>(an, ei, D, id3_ba, id3_ca, cosphi,
                                        g4_etas, g4_zetas, g4_lmdas, out, T, E);
}

// round 2
// speedup vs baseline: 2.3118x; 2.3118x over previous
#include <cuda_runtime.h>

#define NATOMS_MAX 20000
#define NEDGES_MAX 500000
#define LOG2E 1.4426950408889634f
#define PI_OVER_CUT (3.14159265358979323846f / 6.0f)

// scratch (accumulators + packed edge records)
__device__ uint2 g_rec[NEDGES_MAX];
__device__ float g_g2s[NATOMS_MAX * 16];   // [n][src_species][8 etas]
__device__ float g_g4s[NATOMS_MAX * 60];   // [n][trip][18 vals + 2 pad], 16B-aligned blocks

__device__ __forceinline__ float ex2(float x) {
    float y; asm("ex2.approx.ftz.f32 %0, %1;" : "=f"(y) : "f"(x)); return y;
}
__device__ __forceinline__ float lg2(float x) {
    float y; asm("lg2.approx.ftz.f32 %0, %1;" : "=f"(y) : "f"(x)); return y;
}
__device__ __forceinline__ void red4(float* p, float a, float b, float c, float d) {
    asm volatile("red.global.add.v4.f32 [%0], {%1,%2,%3,%4};"
                 :: "l"(p), "f"(a), "f"(b), "f"(c), "f"(d) : "memory");
}
__device__ __forceinline__ void red2(float* p, float a, float b) {
    asm volatile("red.global.add.v2.f32 [%0], {%1,%2};"
                 :: "l"(p), "f"(a), "f"(b) : "memory");
}
__device__ __forceinline__ float fc(float R) {
    return fmaf(0.5f, __cosf(PI_OVER_CUT * R), 0.5f);
}

__global__ void zero_k(int n4_g4, int n4_g2) {
    int i = blockIdx.x * blockDim.x + threadIdx.x;
    float4 z = make_float4(0.f, 0.f, 0.f, 0.f);
    if (i < n4_g4) reinterpret_cast<float4*>(g_g4s)[i] = z;
    if (i < n4_g2) reinterpret_cast<float4*>(g_g2s)[i] = z;
}

// Per edge: build packed record AND accumulate G2 (fused)
__global__ void __launch_bounds__(256) edge_k(const int* __restrict__ an,
                                              const int* __restrict__ ei,
                                              const float* __restrict__ D,
                                              const float* __restrict__ g2_etas,
                                              int E) {
    int e = blockIdx.x * blockDim.x + threadIdx.x;
    if (e >= E) return;
    int src = __ldg(ei + e);
    int tgt = __ldg(ei + E + e);
    int s = __ldg(an + src);
    int t = __ldg(an + tgt);
    float d = __ldg(D + e);

    g_rec[e] = make_uint2(__float_as_uint(d),
                          (unsigned)tgt | ((unsigned)s << 20) | ((unsigned)t << 21));

    float cut = fc(d);
    float md2 = -d * d * LOG2E;
    const float* eta = g2_etas + (s * 2 + t) * 8;
    float v[8];
#pragma unroll
    for (int k = 0; k < 8; k++) v[k] = cut * ex2(md2 * __ldg(eta + k));

    float* o = g_g2s + tgt * 16 + s * 8;
    red4(o,     v[0], v[1], v[2], v[3]);
    red4(o + 4, v[4], v[5], v[6], v[7]);
}

__global__ void __launch_bounds__(256) g4_k(const int* __restrict__ id3_ba,
                                            const int* __restrict__ id3_ca,
                                            const float* __restrict__ cosphi,
                                            const float* __restrict__ g4_etas,
                                            const float* __restrict__ g4_zetas,
                                            const float* __restrict__ g4_lmdas,
                                            int T) {
    int i = blockIdx.x * blockDim.x + threadIdx.x;
    if (i >= T) return;
    int ba = __ldg(id3_ba + i);
    int ca = __ldg(id3_ca + i);
    if (ba <= ca) return;                 // triplet dedup

    float cph = __ldg(cosphi + i);
    uint2 rb = g_rec[ba];
    uint2 rc = g_rec[ca];
    float Rba = __uint_as_float(rb.x);
    float Rca = __uint_as_float(rc.x);
    if (Rba >= 6.0f || Rca >= 6.0f) return;

    float Rbc2 = fmaf(Rba, Rba, fmaf(Rca, Rca, -2.0f * Rba * Rca * cph));
    float Rbc = sqrtf(fmaxf(Rbc2, 1e-12f));
    if (Rbc >= 6.0f) return;

    int aidx = rb.y & 0xFFFFF;
    int A    = (rb.y >> 21) & 1;          // central atom species (an_tgt of ba)
    int sb   = (rb.y >> 20) & 1;
    int sc   = (rc.y >> 20) & 1;
    int t = sb + sc;                      // (0,0)->0 (0,1)/(1,0)->1 (1,1)->2
    int k4 = A * 3 + t;

    float cut3 = fc(Rba) * fc(Rca) * fc(Rbc);
    float r2 = Rbc * Rbc + Rba * Rba + Rca * Rca;

    const float* eta = g4_etas  + k4 * 3;
    const float* zta = g4_zetas + k4 * 3;
    const float* lmd = g4_lmdas + k4 * 2;

    float mr2 = -r2 * LOG2E;
    float rad[3];
#pragma unroll
    for (int ii = 0; ii < 3; ii++) rad[ii] = ex2(mr2 * __ldg(eta + ii)) * cut3;

    float lb[2];
#pragma unroll
    for (int j = 0; j < 2; j++)
        lb[j] = lg2(fmaxf(fabsf(fmaf(__ldg(lmd + j), cph, 1.0f)), 1e-30f));

    float cl[2][3];
#pragma unroll
    for (int j = 0; j < 2; j++)
#pragma unroll
        for (int kk = 0; kk < 3; kk++) {
            float z = __ldg(zta + kk);
            // 2^(1-z) * base^z = exp2(z*lb + (1-z))
            cl[j][kk] = ex2(fmaf(z, lb[j], 1.0f - z));
        }

    float v[18];
#pragma unroll
    for (int ii = 0; ii < 3; ii++)
#pragma unroll
        for (int j = 0; j < 2; j++)
#pragma unroll
            for (int kk = 0; kk < 3; kk++)
                v[(ii * 2 + j) * 3 + kk] = rad[ii] * cl[j][kk];

    float* o = g_g4s + aidx * 60 + t * 20;   // 16B-aligned block of 18 (+2 pad)
    red4(o,      v[0],  v[1],  v[2],  v[3]);
    red4(o + 4,  v[4],  v[5],  v[6],  v[7]);
    red4(o + 8,  v[8],  v[9],  v[10], v[11]);
    red4(o + 12, v[12], v[13], v[14], v[15]);
    red2(o + 16, v[16], v[17]);
}

// Transpose scratch into final [N,70] layout (also replaces zeroing of d_out)
__global__ void combine_k(float* __restrict__ out, int n_total) {
    int i = blockIdx.x * blockDim.x + threadIdx.x;
    if (i >= n_total) return;
    int n = i / 70;
    int c = i % 70;
    float v;
    if (c < 16) {
        v = g_g2s[n * 16 + (c & 1) * 8 + (c >> 1)];     // col = src + 2*eta
    } else {
        int idx = c - 16;                                // col = m*3 + t
        v = g_g4s[n * 60 + (idx % 3) * 20 + (idx / 3)];
    }
    out[i] = v;
}

extern "C" void kernel_launch(void* const* d_in, const int* in_sizes, int n_in,
                              void* d_out, int out_size) {
    const int*   an       = (const int*)  d_in[0];
    const int*   ei       = (const int*)  d_in[1];
    const float* D        = (const float*)d_in[2];
    const int*   id3_ba   = (const int*)  d_in[3];
    const int*   id3_ca   = (const int*)  d_in[4];
    const float* cosphi   = (const float*)d_in[5];
    const float* g2_etas  = (const float*)d_in[6];
    const float* g4_etas  = (const float*)d_in[7];
    const float* g4_zetas = (const float*)d_in[8];
    const float* g4_lmdas = (const float*)d_in[9];

    int E = in_sizes[2];
    int T = in_sizes[3];
    int N = in_sizes[0];
    float* out = (float*)d_out;

    int n4_g4 = N * 60 / 4;
    int n4_g2 = N * 16 / 4;
    int zmax = n4_g4 > n4_g2 ? n4_g4 : n4_g2;

    zero_k<<<(zmax + 255) / 256, 256>>>(n4_g4, n4_g2);
    edge_k<<<(E + 255) / 256, 256>>>(an, ei, D, g2_etas, E);
    g4_k<<<(T + 255) / 256, 256>>>(id3_ba, id3_ca, cosphi,
                                   g4_etas, g4_zetas, g4_lmdas, T);
    combine_k<<<(out_size + 255) / 256, 256>>>(out, out_size);
}